// round 2
// baseline (speedup 1.0000x reference)
#include <cuda_runtime.h>
#include <cstdint>
#include <cmath>

// ---------------- problem constants ----------------
#define NB   4          // batch N
#define LQ   8192       // queries
#define DIM  256        // model dim
#define NHD  8          // heads
#define NLV  4          // levels
#define NPT  4          // points
#define HD   32         // head dim
#define LIN  21760      // sum of level sizes
#define DFF  1024       // 4*D

__device__ __constant__ int c_lvl_h[4]     = {128, 64, 32, 16};
__device__ __constant__ int c_lvl_w[4]     = {128, 64, 32, 16};
__device__ __constant__ int c_lvl_start[4] = {0, 16384, 20480, 21504};

// ---------------- scratch (device globals, no allocation) ----------------
__device__ float g_q    [(size_t)NB * LQ * DIM];      // tgt + query_pos
__device__ float g_value[(size_t)NB * LIN * DIM];     // src @ W_val
__device__ float g_off  [(size_t)NB * LQ * DIM];      // sampling offsets (256/row)
__device__ float g_aw   [(size_t)NB * LQ * 128];      // attention weights (softmaxed)
__device__ float g_attn [(size_t)NB * LQ * DIM];      // sampled output
__device__ float g_y    [(size_t)NB * LQ * DIM];      // tgt + attn_out
__device__ float g_x    [(size_t)NB * LQ * DIM];      // LN1 out
__device__ float g_h    [(size_t)NB * LQ * DFF];      // relu(fc1)
__device__ float g_y2   [(size_t)NB * LQ * DIM];      // x + fc2

// ---------------- elementwise add (float4) ----------------
__global__ void add_kernel(const float* __restrict__ a, const float* __restrict__ b,
                           float* __restrict__ o, int n4) {
    int i = blockIdx.x * blockDim.x + threadIdx.x;
    if (i >= n4) return;
    float4 av = ((const float4*)a)[i];
    float4 bv = ((const float4*)b)[i];
    float4 r  = make_float4(av.x + bv.x, av.y + bv.y, av.z + bv.z, av.w + bv.w);
    ((float4*)o)[i] = r;
}

// ---------------- SGEMM 128x128x8, 256 threads, 8x8 microtile ----------------
// C = A(MxK) @ B(KxN) + bias, with epilogue:
//   epi 0: +bias
//   epi 1: +bias, relu
//   epi 2: +bias, +resid (same shape as C)
//   epi 3: +bias, zero row where mask[row] != 0
#define BM 128
#define BN 128
#define BK 8
#define TM 8
#define TN 8

__global__ __launch_bounds__(256)
void sgemm_kernel(const float* __restrict__ A, const float* __restrict__ B,
                  const float* __restrict__ bias, const float* __restrict__ resid,
                  const unsigned char* __restrict__ mask,
                  float* __restrict__ C, int M, int N, int K, int epi) {
    __shared__ float As[BK][BM];
    __shared__ float Bs[BK][BN];

    const int tid  = threadIdx.x;
    const int cRow = blockIdx.y * BM;
    const int cCol = blockIdx.x * BN;
    const int tx = tid % 16;       // col group
    const int ty = tid / 16;       // row group

    float acc[TM][TN];
#pragma unroll
    for (int i = 0; i < TM; i++)
#pragma unroll
        for (int j = 0; j < TN; j++) acc[i][j] = 0.f;

    const int a_r = tid >> 1;            // 0..127
    const int a_c = (tid & 1) * 4;       // 0 or 4
    const int b_r = tid >> 5;            // 0..7
    const int b_c = (tid & 31) * 4;      // 0..124

    const float* Aptr = A + (size_t)(cRow + a_r) * K + a_c;
    const float* Bptr = B + (size_t)b_r * N + cCol + b_c;

    for (int k0 = 0; k0 < K; k0 += BK) {
        float4 av = *(const float4*)Aptr;
        float4 bv = *(const float4*)Bptr;
        Aptr += BK;
        Bptr += (size_t)BK * N;
        As[a_c + 0][a_r] = av.x;
        As[a_c + 1][a_r] = av.y;
        As[a_c + 2][a_r] = av.z;
        As[a_c + 3][a_r] = av.w;
        *(float4*)&Bs[b_r][b_c] = bv;
        __syncthreads();
#pragma unroll
        for (int kk = 0; kk < BK; kk++) {
            float ar[TM], br[TN];
#pragma unroll
            for (int i = 0; i < TM; i++) ar[i] = As[kk][ty * TM + i];
#pragma unroll
            for (int j = 0; j < TN; j++) br[j] = Bs[kk][tx * TN + j];
#pragma unroll
            for (int i = 0; i < TM; i++)
#pragma unroll
                for (int j = 0; j < TN; j++) acc[i][j] = fmaf(ar[i], br[j], acc[i][j]);
        }
        __syncthreads();
    }

#pragma unroll
    for (int i = 0; i < TM; i++) {
        const int row = cRow + ty * TM + i;
        const unsigned char mz = (epi == 3) ? mask[row] : 0;
#pragma unroll
        for (int j = 0; j < TN; j++) {
            const int col = cCol + tx * TN + j;
            float v = acc[i][j] + bias[col];
            if (epi == 1) v = fmaxf(v, 0.f);
            if (epi == 2) v += resid[(size_t)row * N + col];
            if (epi == 3 && mz) v = 0.f;
            C[(size_t)row * N + col] = v;
        }
    }
}

// ---------------- softmax over groups of 16 ----------------
__global__ void softmax16_kernel(float* __restrict__ aw, int total) {
    int g = blockIdx.x * blockDim.x + threadIdx.x;
    if (g >= total) return;
    float* p = aw + (size_t)g * 16;
    float v[16];
    float m = -1e30f;
#pragma unroll
    for (int i = 0; i < 16; i++) { v[i] = p[i]; m = fmaxf(m, v[i]); }
    float s = 0.f;
#pragma unroll
    for (int i = 0; i < 16; i++) { v[i] = expf(v[i] - m); s += v[i]; }
    float inv = 1.f / s;
#pragma unroll
    for (int i = 0; i < 16; i++) p[i] = v[i] * inv;
}

// ---------------- deformable sampling: warp per (n,lq,head) ----------------
__global__ __launch_bounds__(256)
void sample_kernel(const float* __restrict__ refp, float* __restrict__ out) {
    const int warp_global = (blockIdx.x * blockDim.x + threadIdx.x) >> 5;
    const int lane = threadIdx.x & 31;
    if (warp_global >= NB * LQ * NHD) return;

    const int h = warp_global & (NHD - 1);
    const int q = warp_global >> 3;          // n*LQ + lq
    const int n = q >> 13;                   // LQ = 8192 = 2^13

    const float* offp  = g_off + (size_t)q * 256 + h * 32;   // [l][p][2]
    const float* awp   = g_aw  + (size_t)q * 128 + h * 16;   // [l*4+p]
    const float* ref   = refp  + (size_t)q * (NLV * 2);
    const float* vbase = g_value + (size_t)n * LIN * DIM + h * HD + lane;

    float accum = 0.f;
#pragma unroll
    for (int l = 0; l < NLV; l++) {
        const int H = c_lvl_h[l], W = c_lvl_w[l];
        const float rx = ref[l * 2 + 0];
        const float ry = ref[l * 2 + 1];
        const float* vl = vbase + (size_t)c_lvl_start[l] * DIM;
#pragma unroll
        for (int p = 0; p < NPT; p++) {
            const float ox = offp[(l * 4 + p) * 2 + 0];
            const float oy = offp[(l * 4 + p) * 2 + 1];
            const float a  = awp[l * 4 + p];
            // loc = ref + off/normalizer ; x = loc.x*W - 0.5 ; y = loc.y*H - 0.5
            const float x = (rx + ox / (float)W) * (float)W - 0.5f;
            const float y = (ry + oy / (float)H) * (float)H - 0.5f;
            const float x0 = floorf(x), y0 = floorf(y);
            const float dx = x - x0, dy = y - y0;

            const float cxs[4] = {x0, x0 + 1.f, x0,       x0 + 1.f};
            const float cys[4] = {y0, y0,       y0 + 1.f, y0 + 1.f};
            const float ws[4]  = {(1.f - dx) * (1.f - dy), dx * (1.f - dy),
                                  (1.f - dx) * dy,         dx * dy};
#pragma unroll
            for (int c = 0; c < 4; c++) {
                const float cx = cxs[c], cy = cys[c];
                const bool valid = (cx >= 0.f) && (cx <= (float)(W - 1)) &&
                                   (cy >= 0.f) && (cy <= (float)(H - 1));
                if (valid) {
                    const int ix = (int)fminf(fmaxf(cx, 0.f), (float)(W - 1));
                    const int iy = (int)fminf(fmaxf(cy, 0.f), (float)(H - 1));
                    const float v = vl[(size_t)(iy * W + ix) * DIM];
                    accum = fmaf(a * ws[c], v, accum);
                }
            }
        }
    }
    out[(size_t)q * DIM + h * HD + lane] = accum;
}

// ---------------- layernorm: warp per row, D=256 ----------------
__global__ __launch_bounds__(256)
void ln_kernel(const float* __restrict__ in, const float* __restrict__ gam,
               const float* __restrict__ bet, float* __restrict__ out, int rows) {
    const int warp = (blockIdx.x * blockDim.x + threadIdx.x) >> 5;
    const int lane = threadIdx.x & 31;
    if (warp >= rows) return;
    const float* r = in + (size_t)warp * DIM;
    float v[8];
    float s = 0.f;
#pragma unroll
    for (int j = 0; j < 8; j++) { v[j] = r[j * 32 + lane]; s += v[j]; }
#pragma unroll
    for (int o = 16; o > 0; o >>= 1) s += __shfl_xor_sync(0xffffffffu, s, o);
    const float mean = s * (1.f / 256.f);
    float s2 = 0.f;
#pragma unroll
    for (int j = 0; j < 8; j++) { const float d = v[j] - mean; s2 += d * d; }
#pragma unroll
    for (int o = 16; o > 0; o >>= 1) s2 += __shfl_xor_sync(0xffffffffu, s2, o);
    const float rs = rsqrtf(s2 * (1.f / 256.f) + 1e-5f);
    float* ow = out + (size_t)warp * DIM;
#pragma unroll
    for (int j = 0; j < 8; j++) {
        const int c = j * 32 + lane;
        ow[c] = (v[j] - mean) * rs * gam[c] + bet[c];
    }
}

// ---------------- host launch ----------------
extern "C" void kernel_launch(void* const* d_in, const int* in_sizes, int n_in,
                              void* d_out, int out_size) {
    const float* tgt   = (const float*)d_in[0];
    const float* qpos  = (const float*)d_in[1];
    const float* refp  = (const float*)d_in[2];
    const float* src   = (const float*)d_in[3];
    // d_in[4] = src_spatial_shapes (int64), d_in[5] = level_start_index (int64): constants, unused
    const unsigned char* mask = (const unsigned char*)d_in[6];
    const float* W_off = (const float*)d_in[7];
    const float* b_off = (const float*)d_in[8];
    const float* W_att = (const float*)d_in[9];
    const float* b_att = (const float*)d_in[10];
    const float* W_val = (const float*)d_in[11];
    const float* b_val = (const float*)d_in[12];
    const float* W_out = (const float*)d_in[13];
    const float* b_out = (const float*)d_in[14];
    const float* ln1_g = (const float*)d_in[15];
    const float* ln1_b = (const float*)d_in[16];
    const float* W_fc1 = (const float*)d_in[17];
    const float* b_fc1 = (const float*)d_in[18];
    const float* W_fc2 = (const float*)d_in[19];
    const float* b_fc2 = (const float*)d_in[20];
    const float* ln2_g = (const float*)d_in[21];
    const float* ln2_b = (const float*)d_in[22];
    float* outp = (float*)d_out;

    float *pq, *pvalue, *poff, *paw, *pattn, *py, *px, *ph, *py2;
    cudaGetSymbolAddress((void**)&pq, g_q);
    cudaGetSymbolAddress((void**)&pvalue, g_value);
    cudaGetSymbolAddress((void**)&poff, g_off);
    cudaGetSymbolAddress((void**)&paw, g_aw);
    cudaGetSymbolAddress((void**)&pattn, g_attn);
    cudaGetSymbolAddress((void**)&py, g_y);
    cudaGetSymbolAddress((void**)&px, g_x);
    cudaGetSymbolAddress((void**)&ph, g_h);
    cudaGetSymbolAddress((void**)&py2, g_y2);

    const int MQ = NB * LQ;          // 32768 query rows
    const int MV = NB * LIN;         // 87040 value rows

    // 1. q = tgt + query_pos
    {
        int n4 = MQ * DIM / 4;
        add_kernel<<<(n4 + 255) / 256, 256>>>(tgt, qpos, pq, n4);
    }
    // 2. value = src @ W_val + b_val  (mask rows to zero)
    {
        dim3 grid(DIM / BN, MV / BM);
        sgemm_kernel<<<grid, 256>>>(src, W_val, b_val, nullptr, mask, pvalue,
                                    MV, DIM, DIM, 3);
    }
    // 3. off = q @ W_off + b_off
    {
        dim3 grid(DIM / BN, MQ / BM);
        sgemm_kernel<<<grid, 256>>>(pq, W_off, b_off, nullptr, nullptr, poff,
                                    MQ, DIM, DIM, 0);
    }
    // 4. aw_raw = q @ W_attn + b_attn
    {
        dim3 grid(128 / BN, MQ / BM);
        sgemm_kernel<<<grid, 256>>>(pq, W_att, b_att, nullptr, nullptr, paw,
                                    MQ, 128, DIM, 0);
    }
    // 5. softmax over groups of 16
    {
        int total = MQ * NHD;
        softmax16_kernel<<<(total + 255) / 256, 256>>>(paw, total);
    }
    // 6. deformable sampling -> g_attn
    {
        int total_warps = MQ * NHD;
        int blocks = (total_warps * 32 + 255) / 256;
        sample_kernel<<<blocks, 256>>>(refp, pattn);
    }
    // 7. y = tgt + (attn @ W_out + b_out)
    {
        dim3 grid(DIM / BN, MQ / BM);
        sgemm_kernel<<<grid, 256>>>(pattn, W_out, b_out, tgt, nullptr, py,
                                    MQ, DIM, DIM, 2);
    }
    // 8. x = LN1(y)
    {
        int blocks = (MQ * 32 + 255) / 256;
        ln_kernel<<<blocks, 256>>>(py, ln1_g, ln1_b, px, MQ);
    }
    // 9. h = relu(x @ W_fc1 + b_fc1)
    {
        dim3 grid(DFF / BN, MQ / BM);
        sgemm_kernel<<<grid, 256>>>(px, W_fc1, b_fc1, nullptr, nullptr, ph,
                                    MQ, DFF, DIM, 1);
    }
    // 10. y2 = x + (h @ W_fc2 + b_fc2)
    {
        dim3 grid(DIM / BN, MQ / BM);
        sgemm_kernel<<<grid, 256>>>(ph, W_fc2, b_fc2, px, nullptr, py2,
                                    MQ, DIM, DFF, 2);
    }
    // 11. out = LN2(y2)
    {
        int blocks = (MQ * 32 + 255) / 256;
        ln_kernel<<<blocks, 256>>>(py2, ln2_g, ln2_b, outp, MQ);
    }
}

// round 3
// speedup vs baseline: 2.0214x; 2.0214x over previous
#include <cuda_runtime.h>
#include <cstdint>
#include <cmath>

// ---------------- problem constants ----------------
#define NB   4          // batch N
#define LQ   8192       // queries
#define DIM  256        // model dim
#define NHD  8          // heads
#define NLV  4          // levels
#define NPT  4          // points
#define HD   32         // head dim
#define LIN  21760      // sum of level sizes
#define DFF  1024       // 4*D

__device__ __constant__ int c_lvl_h[4]     = {128, 64, 32, 16};
__device__ __constant__ int c_lvl_w[4]     = {128, 64, 32, 16};
__device__ __constant__ int c_lvl_start[4] = {0, 16384, 20480, 21504};

// ---------------- scratch (device globals, no allocation) ----------------
__device__ float g_q    [(size_t)NB * LQ * DIM];      // tgt + query_pos
__device__ float g_value[(size_t)NB * LIN * DIM];     // src @ W_val
__device__ float g_off  [(size_t)NB * LQ * DIM];      // sampling offsets (256/row)
__device__ float g_aw   [(size_t)NB * LQ * 128];      // attention weights (softmaxed)
__device__ float g_attn [(size_t)NB * LQ * DIM];      // sampled output
__device__ float g_y    [(size_t)NB * LQ * DIM];      // tgt + attn_out
__device__ float g_x    [(size_t)NB * LQ * DIM];      // LN1 out
__device__ float g_h    [(size_t)NB * LQ * DFF];      // relu(fc1)
__device__ float g_y2   [(size_t)NB * LQ * DIM];      // x + fc2

// ---------------- elementwise add (float4) ----------------
__global__ void add_kernel(const float* __restrict__ a, const float* __restrict__ b,
                           float* __restrict__ o, int n4) {
    int i = blockIdx.x * blockDim.x + threadIdx.x;
    if (i >= n4) return;
    float4 av = ((const float4*)a)[i];
    float4 bv = ((const float4*)b)[i];
    float4 r  = make_float4(av.x + bv.x, av.y + bv.y, av.z + bv.z, av.w + bv.w);
    ((float4*)o)[i] = r;
}

// ---------------- TF32 tensor-core GEMM ----------------
// C = A(MxK) @ B(KxN) + bias, epilogues:
//   0: +bias   1: +bias,relu   2: +bias,+resid   3: +bias, zero masked rows
// CTA tile 128x128x16, 8 warps (4x2), warp tile 32x64, mma m16n8k8 tf32.
#define BM 128
#define BN 128
#define BK 16
#define AS_STRIDE 20     // BK + 4  -> conflict-free A fragment reads
#define BS_STRIDE 136    // BN + 8  -> conflict-free B fragment reads

__device__ __forceinline__ unsigned f2tf32(float f) {
    unsigned r;
    asm("cvt.rna.tf32.f32 %0, %1;" : "=r"(r) : "f"(f));
    return r;
}

__device__ __forceinline__ void mma_tf32(float* d, const unsigned* a, const unsigned* b) {
    asm volatile(
        "mma.sync.aligned.m16n8k8.row.col.f32.tf32.tf32.f32 "
        "{%0,%1,%2,%3}, {%4,%5,%6,%7}, {%8,%9}, {%0,%1,%2,%3};"
        : "+f"(d[0]), "+f"(d[1]), "+f"(d[2]), "+f"(d[3])
        : "r"(a[0]), "r"(a[1]), "r"(a[2]), "r"(a[3]), "r"(b[0]), "r"(b[1]));
}

__global__ __launch_bounds__(256, 2)
void tgemm_kernel(const float* __restrict__ A, const float* __restrict__ B,
                  const float* __restrict__ bias, const float* __restrict__ resid,
                  const unsigned char* __restrict__ mask,
                  float* __restrict__ C, int M, int N, int K, int epi) {
    __shared__ unsigned As[BM * AS_STRIDE];   // [m][k] padded
    __shared__ unsigned Bs[BK * BS_STRIDE];   // [k][n] padded

    const int tid  = threadIdx.x;
    const int warp = tid >> 5;
    const int lane = tid & 31;
    const int wm = warp >> 1;      // 0..3  (m)
    const int wn = warp & 1;       // 0..1  (n)
    const int gid = lane >> 2;     // 0..7
    const int tig = lane & 3;      // 0..3

    const int cRow = blockIdx.y * BM;
    const int cCol = blockIdx.x * BN;

    // global-load coordinates (2 float4 each for A and B per thread)
    const int aRow0 = tid >> 2,          aCol0 = (tid & 3) * 4;
    const int aRow1 = (tid + 256) >> 2,  aCol1 = ((tid + 256) & 3) * 4;
    const int bRow0 = tid >> 5,          bCol0 = (tid & 31) * 4;
    const int bRow1 = (tid + 256) >> 5,  bCol1 = ((tid + 256) & 31) * 4;

    const float* Ab = A + (size_t)cRow * K;
    const float* Bb = B + cCol;

    float acc[2][8][4];
#pragma unroll
    for (int mi = 0; mi < 2; mi++)
#pragma unroll
        for (int j = 0; j < 8; j++)
#pragma unroll
            for (int r = 0; r < 4; r++) acc[mi][j][r] = 0.f;

    float4 aR0, aR1, bR0, bR1;

    // prologue: fetch tile 0
    aR0 = *(const float4*)(Ab + (size_t)aRow0 * K + aCol0);
    aR1 = *(const float4*)(Ab + (size_t)aRow1 * K + aCol1);
    bR0 = *(const float4*)(Bb + (size_t)bRow0 * N + bCol0);
    bR1 = *(const float4*)(Bb + (size_t)bRow1 * N + bCol1);

    const int nTiles = K / BK;
    for (int kt = 0; kt < nTiles; kt++) {
        // store fetched tile to smem (convert to tf32)
        {
            unsigned* ap0 = &As[aRow0 * AS_STRIDE + aCol0];
            ap0[0] = f2tf32(aR0.x); ap0[1] = f2tf32(aR0.y);
            ap0[2] = f2tf32(aR0.z); ap0[3] = f2tf32(aR0.w);
            unsigned* ap1 = &As[aRow1 * AS_STRIDE + aCol1];
            ap1[0] = f2tf32(aR1.x); ap1[1] = f2tf32(aR1.y);
            ap1[2] = f2tf32(aR1.z); ap1[3] = f2tf32(aR1.w);
            unsigned* bp0 = &Bs[bRow0 * BS_STRIDE + bCol0];
            bp0[0] = f2tf32(bR0.x); bp0[1] = f2tf32(bR0.y);
            bp0[2] = f2tf32(bR0.z); bp0[3] = f2tf32(bR0.w);
            unsigned* bp1 = &Bs[bRow1 * BS_STRIDE + bCol1];
            bp1[0] = f2tf32(bR1.x); bp1[1] = f2tf32(bR1.y);
            bp1[2] = f2tf32(bR1.z); bp1[3] = f2tf32(bR1.w);
        }
        __syncthreads();

        // prefetch next tile (overlaps with compute below)
        if (kt + 1 < nTiles) {
            const int k0 = (kt + 1) * BK;
            aR0 = *(const float4*)(Ab + (size_t)aRow0 * K + k0 + aCol0);
            aR1 = *(const float4*)(Ab + (size_t)aRow1 * K + k0 + aCol1);
            bR0 = *(const float4*)(Bb + (size_t)(k0 + bRow0) * N + bCol0);
            bR1 = *(const float4*)(Bb + (size_t)(k0 + bRow1) * N + bCol1);
        }

        // compute: 2 k-steps of 8
#pragma unroll
        for (int ks = 0; ks < BK; ks += 8) {
            unsigned afr[2][4];
#pragma unroll
            for (int mi = 0; mi < 2; mi++) {
                const int mrow = wm * 32 + mi * 16 + gid;
                afr[mi][0] = As[mrow * AS_STRIDE + ks + tig];
                afr[mi][1] = As[(mrow + 8) * AS_STRIDE + ks + tig];
                afr[mi][2] = As[mrow * AS_STRIDE + ks + tig + 4];
                afr[mi][3] = As[(mrow + 8) * AS_STRIDE + ks + tig + 4];
            }
            unsigned bfr[8][2];
#pragma unroll
            for (int j = 0; j < 8; j++) {
                const int bcol = wn * 64 + j * 8 + gid;
                bfr[j][0] = Bs[(ks + tig) * BS_STRIDE + bcol];
                bfr[j][1] = Bs[(ks + tig + 4) * BS_STRIDE + bcol];
            }
#pragma unroll
            for (int mi = 0; mi < 2; mi++)
#pragma unroll
                for (int j = 0; j < 8; j++)
                    mma_tf32(acc[mi][j], afr[mi], bfr[j]);
        }
        __syncthreads();
    }

    // epilogue
#pragma unroll
    for (int mi = 0; mi < 2; mi++) {
        const int r0 = cRow + wm * 32 + mi * 16 + gid;
        const int r1 = r0 + 8;
        const unsigned char mz0 = (epi == 3) ? mask[r0] : 0;
        const unsigned char mz1 = (epi == 3) ? mask[r1] : 0;
#pragma unroll
        for (int j = 0; j < 8; j++) {
            const int col = cCol + wn * 64 + j * 8 + tig * 2;
            const float b0 = bias[col], b1 = bias[col + 1];
            float v0 = acc[mi][j][0] + b0;
            float v1 = acc[mi][j][1] + b1;
            float v2 = acc[mi][j][2] + b0;
            float v3 = acc[mi][j][3] + b1;
            if (epi == 1) {
                v0 = fmaxf(v0, 0.f); v1 = fmaxf(v1, 0.f);
                v2 = fmaxf(v2, 0.f); v3 = fmaxf(v3, 0.f);
            }
            if (epi == 2) {
                const float2 rr0 = *(const float2*)&resid[(size_t)r0 * N + col];
                const float2 rr1 = *(const float2*)&resid[(size_t)r1 * N + col];
                v0 += rr0.x; v1 += rr0.y; v2 += rr1.x; v3 += rr1.y;
            }
            if (epi == 3) {
                if (mz0) { v0 = 0.f; v1 = 0.f; }
                if (mz1) { v2 = 0.f; v3 = 0.f; }
            }
            *(float2*)&C[(size_t)r0 * N + col] = make_float2(v0, v1);
            *(float2*)&C[(size_t)r1 * N + col] = make_float2(v2, v3);
        }
    }
}

// ---------------- softmax over groups of 16 ----------------
__global__ void softmax16_kernel(float* __restrict__ aw, int total) {
    int g = blockIdx.x * blockDim.x + threadIdx.x;
    if (g >= total) return;
    float* p = aw + (size_t)g * 16;
    float v[16];
    float m = -1e30f;
#pragma unroll
    for (int i = 0; i < 16; i++) { v[i] = p[i]; m = fmaxf(m, v[i]); }
    float s = 0.f;
#pragma unroll
    for (int i = 0; i < 16; i++) { v[i] = expf(v[i] - m); s += v[i]; }
    float inv = 1.f / s;
#pragma unroll
    for (int i = 0; i < 16; i++) p[i] = v[i] * inv;
}

// ---------------- deformable sampling: warp per (n,lq,head) ----------------
__global__ __launch_bounds__(256)
void sample_kernel(const float* __restrict__ refp, float* __restrict__ out) {
    const int warp_global = (blockIdx.x * blockDim.x + threadIdx.x) >> 5;
    const int lane = threadIdx.x & 31;
    if (warp_global >= NB * LQ * NHD) return;

    const int h = warp_global & (NHD - 1);
    const int q = warp_global >> 3;          // n*LQ + lq
    const int n = q >> 13;                   // LQ = 8192 = 2^13

    const float* offp  = g_off + (size_t)q * 256 + h * 32;   // [l][p][2]
    const float* awp   = g_aw  + (size_t)q * 128 + h * 16;   // [l*4+p]
    const float* ref   = refp  + (size_t)q * (NLV * 2);
    const float* vbase = g_value + (size_t)n * LIN * DIM + h * HD + lane;

    float accum = 0.f;
#pragma unroll
    for (int l = 0; l < NLV; l++) {
        const int H = c_lvl_h[l], W = c_lvl_w[l];
        const float rx = ref[l * 2 + 0];
        const float ry = ref[l * 2 + 1];
        const float* vl = vbase + (size_t)c_lvl_start[l] * DIM;
#pragma unroll
        for (int p = 0; p < NPT; p++) {
            const float ox = offp[(l * 4 + p) * 2 + 0];
            const float oy = offp[(l * 4 + p) * 2 + 1];
            const float a  = awp[l * 4 + p];
            const float x = (rx + ox / (float)W) * (float)W - 0.5f;
            const float y = (ry + oy / (float)H) * (float)H - 0.5f;
            const float x0 = floorf(x), y0 = floorf(y);
            const float dx = x - x0, dy = y - y0;

            const float cxs[4] = {x0, x0 + 1.f, x0,       x0 + 1.f};
            const float cys[4] = {y0, y0,       y0 + 1.f, y0 + 1.f};
            const float ws[4]  = {(1.f - dx) * (1.f - dy), dx * (1.f - dy),
                                  (1.f - dx) * dy,         dx * dy};
#pragma unroll
            for (int c = 0; c < 4; c++) {
                const float cx = cxs[c], cy = cys[c];
                const bool valid = (cx >= 0.f) && (cx <= (float)(W - 1)) &&
                                   (cy >= 0.f) && (cy <= (float)(H - 1));
                if (valid) {
                    const int ix = (int)fminf(fmaxf(cx, 0.f), (float)(W - 1));
                    const int iy = (int)fminf(fmaxf(cy, 0.f), (float)(H - 1));
                    const float v = vl[(size_t)(iy * W + ix) * DIM];
                    accum = fmaf(a * ws[c], v, accum);
                }
            }
        }
    }
    out[(size_t)q * DIM + h * HD + lane] = accum;
}

// ---------------- layernorm: warp per row, D=256 ----------------
__global__ __launch_bounds__(256)
void ln_kernel(const float* __restrict__ in, const float* __restrict__ gam,
               const float* __restrict__ bet, float* __restrict__ out, int rows) {
    const int warp = (blockIdx.x * blockDim.x + threadIdx.x) >> 5;
    const int lane = threadIdx.x & 31;
    if (warp >= rows) return;
    const float* r = in + (size_t)warp * DIM;
    float v[8];
    float s = 0.f;
#pragma unroll
    for (int j = 0; j < 8; j++) { v[j] = r[j * 32 + lane]; s += v[j]; }
#pragma unroll
    for (int o = 16; o > 0; o >>= 1) s += __shfl_xor_sync(0xffffffffu, s, o);
    const float mean = s * (1.f / 256.f);
    float s2 = 0.f;
#pragma unroll
    for (int j = 0; j < 8; j++) { const float d = v[j] - mean; s2 += d * d; }
#pragma unroll
    for (int o = 16; o > 0; o >>= 1) s2 += __shfl_xor_sync(0xffffffffu, s2, o);
    const float rs = rsqrtf(s2 * (1.f / 256.f) + 1e-5f);
    float* ow = out + (size_t)warp * DIM;
#pragma unroll
    for (int j = 0; j < 8; j++) {
        const int c = j * 32 + lane;
        ow[c] = (v[j] - mean) * rs * gam[c] + bet[c];
    }
}

// ---------------- host launch ----------------
extern "C" void kernel_launch(void* const* d_in, const int* in_sizes, int n_in,
                              void* d_out, int out_size) {
    const float* tgt   = (const float*)d_in[0];
    const float* qpos  = (const float*)d_in[1];
    const float* refp  = (const float*)d_in[2];
    const float* src   = (const float*)d_in[3];
    const unsigned char* mask = (const unsigned char*)d_in[6];
    const float* W_off = (const float*)d_in[7];
    const float* b_off = (const float*)d_in[8];
    const float* W_att = (const float*)d_in[9];
    const float* b_att = (const float*)d_in[10];
    const float* W_val = (const float*)d_in[11];
    const float* b_val = (const float*)d_in[12];
    const float* W_out = (const float*)d_in[13];
    const float* b_out = (const float*)d_in[14];
    const float* ln1_g = (const float*)d_in[15];
    const float* ln1_b = (const float*)d_in[16];
    const float* W_fc1 = (const float*)d_in[17];
    const float* b_fc1 = (const float*)d_in[18];
    const float* W_fc2 = (const float*)d_in[19];
    const float* b_fc2 = (const float*)d_in[20];
    const float* ln2_g = (const float*)d_in[21];
    const float* ln2_b = (const float*)d_in[22];
    float* outp = (float*)d_out;

    float *pq, *pvalue, *poff, *paw, *pattn, *py, *px, *ph, *py2;
    cudaGetSymbolAddress((void**)&pq, g_q);
    cudaGetSymbolAddress((void**)&pvalue, g_value);
    cudaGetSymbolAddress((void**)&poff, g_off);
    cudaGetSymbolAddress((void**)&paw, g_aw);
    cudaGetSymbolAddress((void**)&pattn, g_attn);
    cudaGetSymbolAddress((void**)&py, g_y);
    cudaGetSymbolAddress((void**)&px, g_x);
    cudaGetSymbolAddress((void**)&ph, g_h);
    cudaGetSymbolAddress((void**)&py2, g_y2);

    const int MQ = NB * LQ;          // 32768 query rows
    const int MV = NB * LIN;         // 87040 value rows

    // 1. q = tgt + query_pos
    {
        int n4 = MQ * DIM / 4;
        add_kernel<<<(n4 + 255) / 256, 256>>>(tgt, qpos, pq, n4);
    }
    // 2. value = src @ W_val + b_val  (mask rows to zero)
    {
        dim3 grid(DIM / BN, MV / BM);
        tgemm_kernel<<<grid, 256>>>(src, W_val, b_val, nullptr, mask, pvalue,
                                    MV, DIM, DIM, 3);
    }
    // 3. off = q @ W_off + b_off
    {
        dim3 grid(DIM / BN, MQ / BM);
        tgemm_kernel<<<grid, 256>>>(pq, W_off, b_off, nullptr, nullptr, poff,
                                    MQ, DIM, DIM, 0);
    }
    // 4. aw_raw = q @ W_attn + b_attn
    {
        dim3 grid(128 / BN, MQ / BM);
        tgemm_kernel<<<grid, 256>>>(pq, W_att, b_att, nullptr, nullptr, paw,
                                    MQ, 128, DIM, 0);
    }
    // 5. softmax over groups of 16
    {
        int total = MQ * NHD;
        softmax16_kernel<<<(total + 255) / 256, 256>>>(paw, total);
    }
    // 6. deformable sampling -> g_attn
    {
        int total_warps = MQ * NHD;
        int blocks = (total_warps * 32 + 255) / 256;
        sample_kernel<<<blocks, 256>>>(refp, pattn);
    }
    // 7. y = tgt + (attn @ W_out + b_out)
    {
        dim3 grid(DIM / BN, MQ / BM);
        tgemm_kernel<<<grid, 256>>>(pattn, W_out, b_out, tgt, nullptr, py,
                                    MQ, DIM, DIM, 2);
    }
    // 8. x = LN1(y)
    {
        int blocks = (MQ * 32 + 255) / 256;
        ln_kernel<<<blocks, 256>>>(py, ln1_g, ln1_b, px, MQ);
    }
    // 9. h = relu(x @ W_fc1 + b_fc1)
    {
        dim3 grid(DFF / BN, MQ / BM);
        tgemm_kernel<<<grid, 256>>>(px, W_fc1, b_fc1, nullptr, nullptr, ph,
                                    MQ, DFF, DIM, 1);
    }
    // 10. y2 = x + (h @ W_fc2 + b_fc2)
    {
        dim3 grid(DIM / BN, MQ / BM);
        tgemm_kernel<<<grid, 256>>>(ph, W_fc2, b_fc2, px, nullptr, py2,
                                    MQ, DIM, DFF, 2);
    }
    // 11. out = LN2(y2)
    {
        int blocks = (MQ * 32 + 255) / 256;
        ln_kernel<<<blocks, 256>>>(py2, ln2_g, ln2_b, outp, MQ);
    }
}

// round 6
// speedup vs baseline: 2.1000x; 1.0389x over previous
#include <cuda_runtime.h>
#include <cstdint>
#include <cmath>

// ---------------- problem constants ----------------
#define NB   4          // batch N
#define LQ   8192       // queries
#define DIM  256        // model dim
#define NHD  8          // heads
#define NLV  4          // levels
#define NPT  4          // points
#define HD   32         // head dim
#define LIN  21760      // sum of level sizes
#define DFF  1024       // 4*D

__device__ __constant__ int c_lvl_h[4]     = {128, 64, 32, 16};
__device__ __constant__ int c_lvl_w[4]     = {128, 64, 32, 16};
__device__ __constant__ int c_lvl_start[4] = {0, 16384, 20480, 21504};

// ---------------- scratch (device globals, no allocation) ----------------
__device__ float g_q    [(size_t)NB * LQ * DIM];
__device__ float g_value[(size_t)NB * LIN * DIM];
__device__ float g_off  [(size_t)NB * LQ * DIM];
__device__ float g_aw   [(size_t)NB * LQ * 128];
__device__ float g_attn [(size_t)NB * LQ * DIM];
__device__ float g_y    [(size_t)NB * LQ * DIM];
__device__ float g_x    [(size_t)NB * LQ * DIM];
__device__ float g_h    [(size_t)NB * LQ * DFF];
__device__ float g_y2   [(size_t)NB * LQ * DIM];

// ---------------- elementwise add (float4) ----------------
__global__ void add_kernel(const float* __restrict__ a, const float* __restrict__ b,
                           float* __restrict__ o, int n4) {
    int i = blockIdx.x * blockDim.x + threadIdx.x;
    if (i >= n4) return;
    float4 av = ((const float4*)a)[i];
    float4 bv = ((const float4*)b)[i];
    ((float4*)o)[i] = make_float4(av.x + bv.x, av.y + bv.y, av.z + bv.z, av.w + bv.w);
}

// ---------------- TF32 tensor-core GEMM, 2-stage cp.async double buffer -----
// C = A(MxK) @ B(KxN) + bias, epilogues:
//   0: +bias   1: +bias,relu   2: +bias,+resid   3: +bias, zero masked rows
// CTA tile 128x128x16, 8 warps (4x2), warp tile 32x64, mma m16n8k8 tf32.
// fp32 bits fed directly to mma (HW truncates to tf32).
// Static smem (2 stages, 37.9 KB) -- no dynamic smem, no attribute calls.
#define BM 128
#define BN 128
#define BK 16
#define ASTR 20                 // BK + 4   (conflict-free A fragment reads)
#define BSTR 136                // BN + 8   (conflict-free B fragment reads)
#define A_STAGE (BM * ASTR)     // 2560 floats
#define B_STAGE (BK * BSTR)     // 2176 floats
#define STAGE_F (A_STAGE + B_STAGE)   // 4736 floats

__device__ __forceinline__ void cp_async16(uint32_t s, const void* g) {
    asm volatile("cp.async.ca.shared.global [%0], [%1], 16;\n" :: "r"(s), "l"(g));
}
__device__ __forceinline__ void cp_commit() {
    asm volatile("cp.async.commit_group;\n");
}
__device__ __forceinline__ void cp_wait0() {
    asm volatile("cp.async.wait_group 0;\n");
}

__device__ __forceinline__ void mma_tf32(float* d, const unsigned* a, const unsigned* b) {
    asm volatile(
        "mma.sync.aligned.m16n8k8.row.col.f32.tf32.tf32.f32 "
        "{%0,%1,%2,%3}, {%4,%5,%6,%7}, {%8,%9}, {%0,%1,%2,%3};"
        : "+f"(d[0]), "+f"(d[1]), "+f"(d[2]), "+f"(d[3])
        : "r"(a[0]), "r"(a[1]), "r"(a[2]), "r"(a[3]), "r"(b[0]), "r"(b[1]));
}

__global__ __launch_bounds__(256, 2)
void tgemm_kernel(const float* __restrict__ A, const float* __restrict__ B,
                  const float* __restrict__ bias, const float* __restrict__ resid,
                  const unsigned char* __restrict__ mask,
                  float* __restrict__ C, int M, int N, int K, int epi) {
    __shared__ float smem[2 * STAGE_F];   // 37888 bytes, static

    const int tid  = threadIdx.x;
    const int warp = tid >> 5;
    const int lane = tid & 31;
    const int wm = warp >> 1;      // 0..3  (m)
    const int wn = warp & 1;       // 0..1  (n)
    const int gid = lane >> 2;     // 0..7
    const int tig = lane & 3;      // 0..3

    const int cRow = blockIdx.y * BM;
    const int cCol = blockIdx.x * BN;

    // per-thread cp.async assignments: 2 x 16B for A, 2 x 16B for B
    const int aRow0 = tid >> 2;              // 0..63   (+64 for second)
    const int aCol0 = (tid & 3) * 4;         // 0,4,8,12
    const int bRow0 = tid >> 5;              // 0..7    (+8 for second)
    const int bCol0 = (tid & 31) * 4;        // 0..124

    const uint32_t smem_u = (uint32_t)__cvta_generic_to_shared(smem);
    const uint32_t sA0 = smem_u + (uint32_t)(aRow0 * ASTR + aCol0) * 4u;
    const uint32_t sA1 = smem_u + (uint32_t)((aRow0 + 64) * ASTR + aCol0) * 4u;
    const uint32_t sB0 = smem_u + (uint32_t)(A_STAGE + bRow0 * BSTR + bCol0) * 4u;
    const uint32_t sB1 = smem_u + (uint32_t)(A_STAGE + (bRow0 + 8) * BSTR + bCol0) * 4u;

    const float* Ag0 = A + (size_t)(cRow + aRow0) * K + aCol0;
    const float* Ag1 = A + (size_t)(cRow + aRow0 + 64) * K + aCol0;
    const float* Bg0 = B + (size_t)bRow0 * N + cCol + bCol0;
    const float* Bg1 = B + (size_t)(bRow0 + 8) * N + cCol + bCol0;

    float acc[2][8][4];
#pragma unroll
    for (int mi = 0; mi < 2; mi++)
#pragma unroll
        for (int j = 0; j < 8; j++)
#pragma unroll
            for (int r = 0; r < 4; r++) acc[mi][j][r] = 0.f;

    const int nTiles = K / BK;

    // issue one k-tile's copies into smem buffer `buf`
    auto issue = [&](int kt, int buf) {
        const uint32_t so = (uint32_t)(buf * STAGE_F) * 4u;
        const int k0 = kt * BK;
        cp_async16(sA0 + so, Ag0 + k0);
        cp_async16(sA1 + so, Ag1 + k0);
        cp_async16(sB0 + so, Bg0 + (size_t)k0 * N);
        cp_async16(sB1 + so, Bg1 + (size_t)k0 * N);
        cp_commit();
    };

    issue(0, 0);

    for (int kt = 0; kt < nTiles; kt++) {
        cp_wait0();            // all outstanding copies done -> tile kt resident
        __syncthreads();       // visible to all warps; all warps done with buf (kt+1)%2

        if (kt + 1 < nTiles) issue(kt + 1, (kt + 1) & 1);  // overlaps compute below

        const float* As = smem + (kt & 1) * STAGE_F;
        const float* Bs = As + A_STAGE;

#pragma unroll
        for (int ks = 0; ks < BK; ks += 8) {
            unsigned afr[2][4];
#pragma unroll
            for (int mi = 0; mi < 2; mi++) {
                const int mrow = wm * 32 + mi * 16 + gid;
                afr[mi][0] = __float_as_uint(As[mrow * ASTR + ks + tig]);
                afr[mi][1] = __float_as_uint(As[(mrow + 8) * ASTR + ks + tig]);
                afr[mi][2] = __float_as_uint(As[mrow * ASTR + ks + tig + 4]);
                afr[mi][3] = __float_as_uint(As[(mrow + 8) * ASTR + ks + tig + 4]);
            }
            unsigned bfr[8][2];
#pragma unroll
            for (int j = 0; j < 8; j++) {
                const int bcol = wn * 64 + j * 8 + gid;
                bfr[j][0] = __float_as_uint(Bs[(ks + tig) * BSTR + bcol]);
                bfr[j][1] = __float_as_uint(Bs[(ks + tig + 4) * BSTR + bcol]);
            }
#pragma unroll
            for (int mi = 0; mi < 2; mi++)
#pragma unroll
                for (int j = 0; j < 8; j++)
                    mma_tf32(acc[mi][j], afr[mi], bfr[j]);
        }
    }

    // epilogue
#pragma unroll
    for (int mi = 0; mi < 2; mi++) {
        const int r0 = cRow + wm * 32 + mi * 16 + gid;
        const int r1 = r0 + 8;
        const unsigned char mz0 = (epi == 3) ? mask[r0] : 0;
        const unsigned char mz1 = (epi == 3) ? mask[r1] : 0;
#pragma unroll
        for (int j = 0; j < 8; j++) {
            const int col = cCol + wn * 64 + j * 8 + tig * 2;
            const float b0 = bias[col], b1 = bias[col + 1];
            float v0 = acc[mi][j][0] + b0;
            float v1 = acc[mi][j][1] + b1;
            float v2 = acc[mi][j][2] + b0;
            float v3 = acc[mi][j][3] + b1;
            if (epi == 1) {
                v0 = fmaxf(v0, 0.f); v1 = fmaxf(v1, 0.f);
                v2 = fmaxf(v2, 0.f); v3 = fmaxf(v3, 0.f);
            }
            if (epi == 2) {
                const float2 rr0 = *(const float2*)&resid[(size_t)r0 * N + col];
                const float2 rr1 = *(const float2*)&resid[(size_t)r1 * N + col];
                v0 += rr0.x; v1 += rr0.y; v2 += rr1.x; v3 += rr1.y;
            }
            if (epi == 3) {
                if (mz0) { v0 = 0.f; v1 = 0.f; }
                if (mz1) { v2 = 0.f; v3 = 0.f; }
            }
            *(float2*)&C[(size_t)r0 * N + col] = make_float2(v0, v1);
            *(float2*)&C[(size_t)r1 * N + col] = make_float2(v2, v3);
        }
    }
}

// ---------------- softmax over groups of 16 ----------------
__global__ void softmax16_kernel(float* __restrict__ aw, int total) {
    int g = blockIdx.x * blockDim.x + threadIdx.x;
    if (g >= total) return;
    float* p = aw + (size_t)g * 16;
    float v[16];
    float m = -1e30f;
#pragma unroll
    for (int i = 0; i < 16; i++) { v[i] = p[i]; m = fmaxf(m, v[i]); }
    float s = 0.f;
#pragma unroll
    for (int i = 0; i < 16; i++) { v[i] = expf(v[i] - m); s += v[i]; }
    float inv = 1.f / s;
#pragma unroll
    for (int i = 0; i < 16; i++) p[i] = v[i] * inv;
}

// ---------------- deformable sampling: warp per (n,lq,head) ----------------
__global__ __launch_bounds__(256)
void sample_kernel(const float* __restrict__ refp, float* __restrict__ out) {
    const int warp_global = (blockIdx.x * blockDim.x + threadIdx.x) >> 5;
    const int lane = threadIdx.x & 31;
    if (warp_global >= NB * LQ * NHD) return;

    const int h = warp_global & (NHD - 1);
    const int q = warp_global >> 3;
    const int n = q >> 13;

    const float* offp  = g_off + (size_t)q * 256 + h * 32;
    const float* awp   = g_aw  + (size_t)q * 128 + h * 16;
    const float* ref   = refp  + (size_t)q * (NLV * 2);
    const float* vbase = g_value + (size_t)n * LIN * DIM + h * HD + lane;

    float accum = 0.f;
#pragma unroll
    for (int l = 0; l < NLV; l++) {
        const int H = c_lvl_h[l], W = c_lvl_w[l];
        const float rx = ref[l * 2 + 0];
        const float ry = ref[l * 2 + 1];
        const float* vl = vbase + (size_t)c_lvl_start[l] * DIM;
#pragma unroll
        for (int p = 0; p < NPT; p++) {
            const float ox = offp[(l * 4 + p) * 2 + 0];
            const float oy = offp[(l * 4 + p) * 2 + 1];
            const float a  = awp[l * 4 + p];
            const float x = (rx + ox / (float)W) * (float)W - 0.5f;
            const float y = (ry + oy / (float)H) * (float)H - 0.5f;
            const float x0 = floorf(x), y0 = floorf(y);
            const float dx = x - x0, dy = y - y0;

            const float cxs[4] = {x0, x0 + 1.f, x0,       x0 + 1.f};
            const float cys[4] = {y0, y0,       y0 + 1.f, y0 + 1.f};
            const float ws[4]  = {(1.f - dx) * (1.f - dy), dx * (1.f - dy),
                                  (1.f - dx) * dy,         dx * dy};
#pragma unroll
            for (int c = 0; c < 4; c++) {
                const float cx = cxs[c], cy = cys[c];
                const bool valid = (cx >= 0.f) && (cx <= (float)(W - 1)) &&
                                   (cy >= 0.f) && (cy <= (float)(H - 1));
                if (valid) {
                    const int ix = (int)fminf(fmaxf(cx, 0.f), (float)(W - 1));
                    const int iy = (int)fminf(fmaxf(cy, 0.f), (float)(H - 1));
                    const float v = vl[(size_t)(iy * W + ix) * DIM];
                    accum = fmaf(a * ws[c], v, accum);
                }
            }
        }
    }
    out[(size_t)q * DIM + h * HD + lane] = accum;
}

// ---------------- layernorm: warp per row, D=256 ----------------
__global__ __launch_bounds__(256)
void ln_kernel(const float* __restrict__ in, const float* __restrict__ gam,
               const float* __restrict__ bet, float* __restrict__ out, int rows) {
    const int warp = (blockIdx.x * blockDim.x + threadIdx.x) >> 5;
    const int lane = threadIdx.x & 31;
    if (warp >= rows) return;
    const float* r = in + (size_t)warp * DIM;
    float v[8];
    float s = 0.f;
#pragma unroll
    for (int j = 0; j < 8; j++) { v[j] = r[j * 32 + lane]; s += v[j]; }
#pragma unroll
    for (int o = 16; o > 0; o >>= 1) s += __shfl_xor_sync(0xffffffffu, s, o);
    const float mean = s * (1.f / 256.f);
    float s2 = 0.f;
#pragma unroll
    for (int j = 0; j < 8; j++) { const float d = v[j] - mean; s2 += d * d; }
#pragma unroll
    for (int o = 16; o > 0; o >>= 1) s2 += __shfl_xor_sync(0xffffffffu, s2, o);
    const float rs = rsqrtf(s2 * (1.f / 256.f) + 1e-5f);
    float* ow = out + (size_t)warp * DIM;
#pragma unroll
    for (int j = 0; j < 8; j++) {
        const int c = j * 32 + lane;
        ow[c] = (v[j] - mean) * rs * gam[c] + bet[c];
    }
}

// ---------------- host launch ----------------
extern "C" void kernel_launch(void* const* d_in, const int* in_sizes, int n_in,
                              void* d_out, int out_size) {
    const float* tgt   = (const float*)d_in[0];
    const float* qpos  = (const float*)d_in[1];
    const float* refp  = (const float*)d_in[2];
    const float* src   = (const float*)d_in[3];
    const unsigned char* mask = (const unsigned char*)d_in[6];
    const float* W_off = (const float*)d_in[7];
    const float* b_off = (const float*)d_in[8];
    const float* W_att = (const float*)d_in[9];
    const float* b_att = (const float*)d_in[10];
    const float* W_val = (const float*)d_in[11];
    const float* b_val = (const float*)d_in[12];
    const float* W_out = (const float*)d_in[13];
    const float* b_out = (const float*)d_in[14];
    const float* ln1_g = (const float*)d_in[15];
    const float* ln1_b = (const float*)d_in[16];
    const float* W_fc1 = (const float*)d_in[17];
    const float* b_fc1 = (const float*)d_in[18];
    const float* W_fc2 = (const float*)d_in[19];
    const float* b_fc2 = (const float*)d_in[20];
    const float* ln2_g = (const float*)d_in[21];
    const float* ln2_b = (const float*)d_in[22];
    float* outp = (float*)d_out;

    float *pq, *pvalue, *poff, *paw, *pattn, *py, *px, *ph, *py2;
    cudaGetSymbolAddress((void**)&pq, g_q);
    cudaGetSymbolAddress((void**)&pvalue, g_value);
    cudaGetSymbolAddress((void**)&poff, g_off);
    cudaGetSymbolAddress((void**)&paw, g_aw);
    cudaGetSymbolAddress((void**)&pattn, g_attn);
    cudaGetSymbolAddress((void**)&py, g_y);
    cudaGetSymbolAddress((void**)&px, g_x);
    cudaGetSymbolAddress((void**)&ph, g_h);
    cudaGetSymbolAddress((void**)&py2, g_y2);

    const int MQ = NB * LQ;          // 32768
    const int MV = NB * LIN;         // 87040

    // 1. q = tgt + query_pos
    {
        int n4 = MQ * DIM / 4;
        add_kernel<<<(n4 + 255) / 256, 256>>>(tgt, qpos, pq, n4);
    }
    // 2. value = src @ W_val + b_val  (mask rows to zero)
    {
        dim3 grid(DIM / BN, MV / BM);
        tgemm_kernel<<<grid, 256>>>(src, W_val, b_val, nullptr, mask,
                                    pvalue, MV, DIM, DIM, 3);
    }
    // 3. off = q @ W_off + b_off
    {
        dim3 grid(DIM / BN, MQ / BM);
        tgemm_kernel<<<grid, 256>>>(pq, W_off, b_off, nullptr, nullptr,
                                    poff, MQ, DIM, DIM, 0);
    }
    // 4. aw_raw = q @ W_attn + b_attn
    {
        dim3 grid(128 / BN, MQ / BM);
        tgemm_kernel<<<grid, 256>>>(pq, W_att, b_att, nullptr, nullptr,
                                    paw, MQ, 128, DIM, 0);
    }
    // 5. softmax over groups of 16
    {
        int total = MQ * NHD;
        softmax16_kernel<<<(total + 255) / 256, 256>>>(paw, total);
    }
    // 6. deformable sampling -> g_attn
    {
        int total_warps = MQ * NHD;
        int blocks = (total_warps * 32 + 255) / 256;
        sample_kernel<<<blocks, 256>>>(refp, pattn);
    }
    // 7. y = tgt + (attn @ W_out + b_out)
    {
        dim3 grid(DIM / BN, MQ / BM);
        tgemm_kernel<<<grid, 256>>>(pattn, W_out, b_out, tgt, nullptr,
                                    py, MQ, DIM, DIM, 2);
    }
    // 8. x = LN1(y)
    {
        int blocks = (MQ * 32 + 255) / 256;
        ln_kernel<<<blocks, 256>>>(py, ln1_g, ln1_b, px, MQ);
    }
    // 9. h = relu(x @ W_fc1 + b_fc1)
    {
        dim3 grid(DFF / BN, MQ / BM);
        tgemm_kernel<<<grid, 256>>>(px, W_fc1, b_fc1, nullptr, nullptr,
                                    ph, MQ, DFF, DIM, 1);
    }
    // 10. y2 = x + (h @ W_fc2 + b_fc2)
    {
        dim3 grid(DIM / BN, MQ / BM);
        tgemm_kernel<<<grid, 256>>>(ph, W_fc2, b_fc2, px, nullptr,
                                    py2, MQ, DIM, DFF, 2);
    }
    // 11. out = LN2(y2)
    {
        int blocks = (MQ * 32 + 255) / 256;
        ln_kernel<<<blocks, 256>>>(py2, ln2_g, ln2_b, outp, MQ);
    }
}